// round 4
// baseline (speedup 1.0000x reference)
#include <cuda_runtime.h>
#include <cstdint>

// ============================================================
// Fused 4-layer MLP via mma.sync m16n8k8 tf32 (sm_100 base target;
// tcgen05 unavailable: harness compiles to .target sm_100).
//   out = relu( ((relu(x@W0^T)) @ W1^T @ W2^T) @ W3^T )
// Each warp carries 16 rows through all layers in registers.
// C-frag -> next A-frag via register relabel + K-permuted weights.
// ============================================================

#define THREADS 128          // 4 warps/CTA
#define TILE_ROWS 64         // 4 warps x 16 rows
#define CTAS_PER_SM 3

// SMEM weight strides (floats) — conflict-free for lds pattern (8j+r)*S + 8t+m
#define S0 36   // W0: 64 x 32 (padded)
#define S1 68   // W1: 64 x 64 (padded)
#define S3 68   // W3: 16 x 64 (padded)

static __device__ __forceinline__ uint32_t to_tf32(float f) {
    uint32_t u;
    asm("cvt.rna.tf32.f32 %0, %1;" : "=r"(u) : "f"(f));
    return u;
}

static __device__ __forceinline__ void mma8(float c[4],
                                            uint32_t a0, uint32_t a1, uint32_t a2, uint32_t a3,
                                            uint32_t b0, uint32_t b1) {
    asm volatile(
        "mma.sync.aligned.m16n8k8.row.col.f32.tf32.tf32.f32 "
        "{%0,%1,%2,%3}, {%4,%5,%6,%7}, {%8,%9}, {%0,%1,%2,%3};"
        : "+f"(c[0]), "+f"(c[1]), "+f"(c[2]), "+f"(c[3])
        : "r"(a0), "r"(a1), "r"(a2), "r"(a3), "r"(b0), "r"(b1));
}

// K-permutation within each 8-group that compensates the C->A relabel:
// consuming MMA col p reads hidden col perm(p).
static __device__ __forceinline__ int kperm(int p) {
    return (p < 4) ? 2 * p : 2 * (p - 4) + 1;
}

__global__ void __launch_bounds__(THREADS, CTAS_PER_SM)
ffmlp_kernel(const float* __restrict__ x,
             const float* __restrict__ W0, const float* __restrict__ W1,
             const float* __restrict__ W2, const float* __restrict__ W3,
             float* __restrict__ out, int Brows) {
    __shared__ uint32_t w0s[64 * S0];
    __shared__ uint32_t w1s[64 * S1];
    __shared__ uint32_t w2s[64 * S1];
    __shared__ uint32_t w3s[16 * S3];

    const int tid = threadIdx.x;

    // ---- stage weights (tf32, K-permuted for layers 1..3) ----
    for (int i = tid; i < 64 * 32; i += THREADS) {
        int n = i >> 5, k = i & 31;
        w0s[n * S0 + k] = to_tf32(__ldg(W0 + n * 32 + k));   // layer 0: natural K
    }
    for (int i = tid; i < 64 * 64; i += THREADS) {
        int n = i >> 6, kp = i & 63;
        int src = (kp & ~7) + kperm(kp & 7);
        w1s[n * S1 + kp] = to_tf32(__ldg(W1 + n * 64 + src));
        w2s[n * S1 + kp] = to_tf32(__ldg(W2 + n * 64 + src));
    }
    for (int i = tid; i < 16 * 64; i += THREADS) {
        int n = i >> 6, kp = i & 63;
        int src = (kp & ~7) + kperm(kp & 7);
        w3s[n * S3 + kp] = to_tf32(__ldg(W3 + n * 64 + src));
    }
    __syncthreads();

    const int wid  = tid >> 5;
    const int lane = tid & 31;
    const int r = lane >> 2;      // group id (row within 8)
    const int m = lane & 3;       // thread-in-group (col base)

    const int ntiles = Brows / TILE_ROWS;   // B = 1M -> exact

    for (int tile = blockIdx.x; tile < ntiles; tile += gridDim.x) {
        const int row0 = tile * TILE_ROWS + wid * 16;

        // ---- x fragments: A for layer 0 (natural K order) ----
        uint32_t xa[4][4];
        const float* xr0 = x + (size_t)(row0 + r) * 32;
        const float* xr8 = x + (size_t)(row0 + r + 8) * 32;
#pragma unroll
        for (int t = 0; t < 4; t++) {
            xa[t][0] = to_tf32(__ldg(xr0 + 8 * t + m));
            xa[t][1] = to_tf32(__ldg(xr8 + 8 * t + m));
            xa[t][2] = to_tf32(__ldg(xr0 + 8 * t + m + 4));
            xa[t][3] = to_tf32(__ldg(xr8 + 8 * t + m + 4));
        }

        // ---- Layer 0: [16,32] x [32,64] ----
        float c[8][4];
#pragma unroll
        for (int j = 0; j < 8; j++) { c[j][0] = c[j][1] = c[j][2] = c[j][3] = 0.f; }
#pragma unroll
        for (int t = 0; t < 4; t++) {
#pragma unroll
            for (int j = 0; j < 8; j++) {
                uint32_t b0 = w0s[(8 * j + r) * S0 + 8 * t + m];
                uint32_t b1 = w0s[(8 * j + r) * S0 + 8 * t + m + 4];
                mma8(c[j], xa[t][0], xa[t][1], xa[t][2], xa[t][3], b0, b1);
            }
        }

        // ReLU + tf32-quantize -> A fragments for layer 1 (relabel c0,c2,c1,c3)
        uint32_t a[8][4];
#pragma unroll
        for (int j = 0; j < 8; j++) {
            a[j][0] = to_tf32(fmaxf(c[j][0], 0.f));
            a[j][1] = to_tf32(fmaxf(c[j][2], 0.f));
            a[j][2] = to_tf32(fmaxf(c[j][1], 0.f));
            a[j][3] = to_tf32(fmaxf(c[j][3], 0.f));
        }

        // ---- Layer 1: [16,64] x [64,64] (no activation) ----
#pragma unroll
        for (int j = 0; j < 8; j++) { c[j][0] = c[j][1] = c[j][2] = c[j][3] = 0.f; }
#pragma unroll
        for (int t = 0; t < 8; t++) {
#pragma unroll
            for (int j = 0; j < 8; j++) {
                uint32_t b0 = w1s[(8 * j + r) * S1 + 8 * t + m];
                uint32_t b1 = w1s[(8 * j + r) * S1 + 8 * t + m + 4];
                mma8(c[j], a[t][0], a[t][1], a[t][2], a[t][3], b0, b1);
            }
        }
#pragma unroll
        for (int j = 0; j < 8; j++) {
            a[j][0] = to_tf32(c[j][0]);
            a[j][1] = to_tf32(c[j][2]);
            a[j][2] = to_tf32(c[j][1]);
            a[j][3] = to_tf32(c[j][3]);
        }

        // ---- Layer 2: [16,64] x [64,64] (no activation) ----
#pragma unroll
        for (int j = 0; j < 8; j++) { c[j][0] = c[j][1] = c[j][2] = c[j][3] = 0.f; }
#pragma unroll
        for (int t = 0; t < 8; t++) {
#pragma unroll
            for (int j = 0; j < 8; j++) {
                uint32_t b0 = w2s[(8 * j + r) * S1 + 8 * t + m];
                uint32_t b1 = w2s[(8 * j + r) * S1 + 8 * t + m + 4];
                mma8(c[j], a[t][0], a[t][1], a[t][2], a[t][3], b0, b1);
            }
        }
#pragma unroll
        for (int j = 0; j < 8; j++) {
            a[j][0] = to_tf32(c[j][0]);
            a[j][1] = to_tf32(c[j][2]);
            a[j][2] = to_tf32(c[j][1]);
            a[j][3] = to_tf32(c[j][3]);
        }

        // ---- Layer 3: [16,64] x [64,16] ----
        float c3[2][4];
#pragma unroll
        for (int j = 0; j < 2; j++) { c3[j][0] = c3[j][1] = c3[j][2] = c3[j][3] = 0.f; }
#pragma unroll
        for (int t = 0; t < 8; t++) {
#pragma unroll
            for (int j = 0; j < 2; j++) {
                uint32_t b0 = w3s[(8 * j + r) * S3 + 8 * t + m];
                uint32_t b1 = w3s[(8 * j + r) * S3 + 8 * t + m + 4];
                mma8(c3[j], a[t][0], a[t][1], a[t][2], a[t][3], b0, b1);
            }
        }

        // ---- Epilogue: ReLU + store (natural N order; C layout is coalescable) ----
        float* o0 = out + (size_t)(row0 + r) * 16;
        float* o8 = out + (size_t)(row0 + r + 8) * 16;
#pragma unroll
        for (int j = 0; j < 2; j++) {
            float2 v0 = make_float2(fmaxf(c3[j][0], 0.f), fmaxf(c3[j][1], 0.f));
            float2 v1 = make_float2(fmaxf(c3[j][2], 0.f), fmaxf(c3[j][3], 0.f));
            *reinterpret_cast<float2*>(o0 + 8 * j + 2 * m) = v0;
            *reinterpret_cast<float2*>(o8 + 8 * j + 2 * m) = v1;
        }
    }
}

extern "C" void kernel_launch(void* const* d_in, const int* in_sizes, int n_in,
                              void* d_out, int out_size) {
    const float* x  = (const float*)d_in[0];
    const float* W0 = (const float*)d_in[1];
    const float* W1 = (const float*)d_in[2];
    const float* W2 = (const float*)d_in[3];
    const float* W3 = (const float*)d_in[4];
    float* out = (float*)d_out;
    int Brows = in_sizes[0] / 32;

    int ntiles = Brows / TILE_ROWS;
    int grid = CTAS_PER_SM * 148;
    if (grid > ntiles) grid = ntiles;
    if (grid < 1) grid = 1;
    ffmlp_kernel<<<grid, THREADS>>>(x, W0, W1, W2, W3, out, Brows);
}

// round 6
// speedup vs baseline: 2.3250x; 2.3250x over previous
#include <cuda_runtime.h>
#include <cuda_fp16.h>
#include <cstdint>

// ============================================================
// Fused 4-layer MLP via mma.sync m16n8k16 f16 (fp32 accum).
//   out = relu( ((relu(x@W0^T)) @ W1^T @ W2^T) @ W3^T )
// Each warp carries 2x16 rows through all layers in registers.
// C-frag pair {2m,2m+1} == next A fp16x2 slot -> zero-cost chain.
// B fragments packed as uint4 in SMEM: 1 LDS.128 -> 4 MMAs.
// ============================================================

#define THREADS 128          // 4 warps/CTA
#define ROWS_PER_WARP 32     // 2 x m16 subtiles
#define TILE_ROWS 128        // 4 warps x 32 rows
#define CTAS_PER_SM 3

static __device__ __forceinline__ uint32_t f22h2(float lo, float hi) {
    __half2 h = __floats2half2_rn(lo, hi);   // lo -> .x (low half)
    return *reinterpret_cast<uint32_t*>(&h);
}

static __device__ __forceinline__ void mma16(float c[4], const uint32_t a[4],
                                             uint32_t b0, uint32_t b1) {
    asm volatile(
        "mma.sync.aligned.m16n8k16.row.col.f32.f16.f16.f32 "
        "{%0,%1,%2,%3}, {%4,%5,%6,%7}, {%8,%9}, {%0,%1,%2,%3};"
        : "+f"(c[0]), "+f"(c[1]), "+f"(c[2]), "+f"(c[3])
        : "r"(a[0]), "r"(a[1]), "r"(a[2]), "r"(a[3]), "r"(b0), "r"(b1));
}

__global__ void __launch_bounds__(THREADS, CTAS_PER_SM)
ffmlp_kernel(const float* __restrict__ x,
             const float* __restrict__ W0, const float* __restrict__ W1,
             const float* __restrict__ W2, const float* __restrict__ W3,
             float* __restrict__ out, int Brows) {
    // Packed B fragments: uint4 = {b0(n0), b1(n0), b0(n1), b1(n1)} (fp16x2 each)
    // index [u][j2][r][m]: u = k16 chunk, j2 = n-chunk pair, (r,m) = lane
    __shared__ uint4 w0p[2 * 4 * 8 * 4];   // 256  (4 KB)  L0: K=32 -> u:2
    __shared__ uint4 w1p[4 * 4 * 8 * 4];   // 512  (8 KB)  L1: K=64 -> u:4
    __shared__ uint4 w2p[4 * 4 * 8 * 4];   // 512  (8 KB)
    __shared__ uint4 w3p[4 * 1 * 8 * 4];   // 128  (2 KB)  L3: 16 outputs -> j2:1

    const int tid = threadIdx.x;

    // ---- stage weights (fp16 pairs) ----
    // L0 with x-load permutation sigma0: B slot (u,m) pair0 <- cols 8m+4u, +1;
    // pair1 <- cols 8m+4u+2, +3  (matches float4 x loads below)
    for (int i = tid; i < 256; i += THREADS) {
        int u = i >> 7, j2 = (i >> 5) & 3, r = (i >> 2) & 7, m = i & 3;
        int n0 = 16 * j2 + r, n1 = n0 + 8;
        int k = 8 * m + 4 * u;
        const float* p0 = W0 + n0 * 32 + k;
        const float* p1 = W0 + n1 * 32 + k;
        uint4 v;
        v.x = f22h2(__ldg(p0 + 0), __ldg(p0 + 1));
        v.y = f22h2(__ldg(p0 + 2), __ldg(p0 + 3));
        v.z = f22h2(__ldg(p1 + 0), __ldg(p1 + 1));
        v.w = f22h2(__ldg(p1 + 2), __ldg(p1 + 3));
        w0p[i] = v;
    }
    // L1/L2: natural layout (C->A chain needs no permutation for f16 pairs)
    for (int i = tid; i < 512; i += THREADS) {
        int u = i >> 7, j2 = (i >> 5) & 3, r = (i >> 2) & 7, m = i & 3;
        int n0 = 16 * j2 + r, n1 = n0 + 8;
        int k0 = 16 * u + 2 * m;
        uint4 v;
        v.x = f22h2(__ldg(W1 + n0 * 64 + k0),     __ldg(W1 + n0 * 64 + k0 + 1));
        v.y = f22h2(__ldg(W1 + n0 * 64 + k0 + 8), __ldg(W1 + n0 * 64 + k0 + 9));
        v.z = f22h2(__ldg(W1 + n1 * 64 + k0),     __ldg(W1 + n1 * 64 + k0 + 1));
        v.w = f22h2(__ldg(W1 + n1 * 64 + k0 + 8), __ldg(W1 + n1 * 64 + k0 + 9));
        w1p[i] = v;
        v.x = f22h2(__ldg(W2 + n0 * 64 + k0),     __ldg(W2 + n0 * 64 + k0 + 1));
        v.y = f22h2(__ldg(W2 + n0 * 64 + k0 + 8), __ldg(W2 + n0 * 64 + k0 + 9));
        v.z = f22h2(__ldg(W2 + n1 * 64 + k0),     __ldg(W2 + n1 * 64 + k0 + 1));
        v.w = f22h2(__ldg(W2 + n1 * 64 + k0 + 8), __ldg(W2 + n1 * 64 + k0 + 9));
        w2p[i] = v;
    }
    for (int i = tid; i < 128; i += THREADS) {
        int u = i >> 5, r = (i >> 2) & 7, m = i & 3;
        int n0 = r, n1 = r + 8;
        int k0 = 16 * u + 2 * m;
        uint4 v;
        v.x = f22h2(__ldg(W3 + n0 * 64 + k0),     __ldg(W3 + n0 * 64 + k0 + 1));
        v.y = f22h2(__ldg(W3 + n0 * 64 + k0 + 8), __ldg(W3 + n0 * 64 + k0 + 9));
        v.z = f22h2(__ldg(W3 + n1 * 64 + k0),     __ldg(W3 + n1 * 64 + k0 + 1));
        v.w = f22h2(__ldg(W3 + n1 * 64 + k0 + 8), __ldg(W3 + n1 * 64 + k0 + 9));
        w3p[i] = v;
    }
    __syncthreads();

    const int wid  = tid >> 5;
    const int lane = tid & 31;
    const int r = lane >> 2;      // group id (row within 8)
    const int m = lane & 3;       // thread-in-group
    const int lidx = r * 4 + m;   // packed (r,m) index

    const int ntiles = Brows / TILE_ROWS;   // B = 1M -> exact

    for (int tile = blockIdx.x; tile < ntiles; tile += gridDim.x) {
        const int row0 = tile * TILE_ROWS + wid * ROWS_PER_WARP;

        // ---- x fragments (float4 loads, sigma0-permuted K) ----
        uint32_t xa[2][2][4];
#pragma unroll
        for (int s = 0; s < 2; s++) {
            int base = row0 + 16 * s;
            const float4* q0 = reinterpret_cast<const float4*>(x + (size_t)(base + r) * 32 + 8 * m);
            const float4* q1 = reinterpret_cast<const float4*>(x + (size_t)(base + r + 8) * 32 + 8 * m);
            float4 lo0 = q0[0], hi0 = q0[1];
            float4 lo1 = q1[0], hi1 = q1[1];
            xa[s][0][0] = f22h2(lo0.x, lo0.y);  xa[s][0][2] = f22h2(lo0.z, lo0.w);
            xa[s][1][0] = f22h2(hi0.x, hi0.y);  xa[s][1][2] = f22h2(hi0.z, hi0.w);
            xa[s][0][1] = f22h2(lo1.x, lo1.y);  xa[s][0][3] = f22h2(lo1.z, lo1.w);
            xa[s][1][1] = f22h2(hi1.x, hi1.y);  xa[s][1][3] = f22h2(hi1.z, hi1.w);
        }

        // ---- Layer 0: [32,32] x [32,64] ----
        float c[2][8][4];
#pragma unroll
        for (int s = 0; s < 2; s++)
#pragma unroll
            for (int j = 0; j < 8; j++) { c[s][j][0] = c[s][j][1] = c[s][j][2] = c[s][j][3] = 0.f; }
#pragma unroll
        for (int u = 0; u < 2; u++) {
#pragma unroll
            for (int j2 = 0; j2 < 4; j2++) {
                uint4 bb = w0p[((u * 4 + j2) * 32) + lidx];
#pragma unroll
                for (int s = 0; s < 2; s++) {
                    mma16(c[s][2 * j2],     xa[s][u], bb.x, bb.y);
                    mma16(c[s][2 * j2 + 1], xa[s][u], bb.z, bb.w);
                }
            }
        }

        // ReLU + pack -> A for layer 1
        uint32_t a[2][4][4];
#pragma unroll
        for (int s = 0; s < 2; s++)
#pragma unroll
            for (int u = 0; u < 4; u++) {
                a[s][u][0] = f22h2(fmaxf(c[s][2*u][0], 0.f),   fmaxf(c[s][2*u][1], 0.f));
                a[s][u][1] = f22h2(fmaxf(c[s][2*u][2], 0.f),   fmaxf(c[s][2*u][3], 0.f));
                a[s][u][2] = f22h2(fmaxf(c[s][2*u+1][0], 0.f), fmaxf(c[s][2*u+1][1], 0.f));
                a[s][u][3] = f22h2(fmaxf(c[s][2*u+1][2], 0.f), fmaxf(c[s][2*u+1][3], 0.f));
            }

        // ---- Layer 1: [32,64] x [64,64] (no activation) ----
#pragma unroll
        for (int s = 0; s < 2; s++)
#pragma unroll
            for (int j = 0; j < 8; j++) { c[s][j][0] = c[s][j][1] = c[s][j][2] = c[s][j][3] = 0.f; }
#pragma unroll
        for (int u = 0; u < 4; u++) {
#pragma unroll
            for (int j2 = 0; j2 < 4; j2++) {
                uint4 bb = w1p[((u * 4 + j2) * 32) + lidx];
#pragma unroll
                for (int s = 0; s < 2; s++) {
                    mma16(c[s][2 * j2],     a[s][u], bb.x, bb.y);
                    mma16(c[s][2 * j2 + 1], a[s][u], bb.z, bb.w);
                }
            }
        }
#pragma unroll
        for (int s = 0; s < 2; s++)
#pragma unroll
            for (int u = 0; u < 4; u++) {
                a[s][u][0] = f22h2(c[s][2*u][0],   c[s][2*u][1]);
                a[s][u][1] = f22h2(c[s][2*u][2],   c[s][2*u][3]);
                a[s][u][2] = f22h2(c[s][2*u+1][0], c[s][2*u+1][1]);
                a[s][u][3] = f22h2(c[s][2*u+1][2], c[s][2*u+1][3]);
            }

        // ---- Layer 2: [32,64] x [64,64] (no activation) ----
#pragma unroll
        for (int s = 0; s < 2; s++)
#pragma unroll
            for (int j = 0; j < 8; j++) { c[s][j][0] = c[s][j][1] = c[s][j][2] = c[s][j][3] = 0.f; }
#pragma unroll
        for (int u = 0; u < 4; u++) {
#pragma unroll
            for (int j2 = 0; j2 < 4; j2++) {
                uint4 bb = w2p[((u * 4 + j2) * 32) + lidx];
#pragma unroll
                for (int s = 0; s < 2; s++) {
                    mma16(c[s][2 * j2],     a[s][u], bb.x, bb.y);
                    mma16(c[s][2 * j2 + 1], a[s][u], bb.z, bb.w);
                }
            }
        }
#pragma unroll
        for (int s = 0; s < 2; s++)
#pragma unroll
            for (int u = 0; u < 4; u++) {
                a[s][u][0] = f22h2(c[s][2*u][0],   c[s][2*u][1]);
                a[s][u][1] = f22h2(c[s][2*u][2],   c[s][2*u][3]);
                a[s][u][2] = f22h2(c[s][2*u+1][0], c[s][2*u+1][1]);
                a[s][u][3] = f22h2(c[s][2*u+1][2], c[s][2*u+1][3]);
            }

        // ---- Layer 3: [32,64] x [64,16] ----
        float c3[2][2][4];
#pragma unroll
        for (int s = 0; s < 2; s++)
#pragma unroll
            for (int j = 0; j < 2; j++) { c3[s][j][0] = c3[s][j][1] = c3[s][j][2] = c3[s][j][3] = 0.f; }
#pragma unroll
        for (int u = 0; u < 4; u++) {
            uint4 bb = w3p[(u * 32) + lidx];
#pragma unroll
            for (int s = 0; s < 2; s++) {
                mma16(c3[s][0], a[s][u], bb.x, bb.y);
                mma16(c3[s][1], a[s][u], bb.z, bb.w);
            }
        }

        // ---- Epilogue: ReLU + store ----
#pragma unroll
        for (int s = 0; s < 2; s++) {
            int base = row0 + 16 * s;
            float* o0 = out + (size_t)(base + r) * 16;
            float* o8 = out + (size_t)(base + r + 8) * 16;
#pragma unroll
            for (int j = 0; j < 2; j++) {
                float2 v0 = make_float2(fmaxf(c3[s][j][0], 0.f), fmaxf(c3[s][j][1], 0.f));
                float2 v1 = make_float2(fmaxf(c3[s][j][2], 0.f), fmaxf(c3[s][j][3], 0.f));
                *reinterpret_cast<float2*>(o0 + 8 * j + 2 * m) = v0;
                *reinterpret_cast<float2*>(o8 + 8 * j + 2 * m) = v1;
            }
        }
    }
}

extern "C" void kernel_launch(void* const* d_in, const int* in_sizes, int n_in,
                              void* d_out, int out_size) {
    const float* x  = (const float*)d_in[0];
    const float* W0 = (const float*)d_in[1];
    const float* W1 = (const float*)d_in[2];
    const float* W2 = (const float*)d_in[3];
    const float* W3 = (const float*)d_in[4];
    float* out = (float*)d_out;
    int Brows = in_sizes[0] / 32;

    int ntiles = Brows / TILE_ROWS;
    int grid = CTAS_PER_SM * 148;
    if (grid > ntiles) grid = ntiles;
    if (grid < 1) grid = 1;
    ffmlp_kernel<<<grid, THREADS>>>(x, W0, W1, W2, W3, out, Brows);
}

// round 7
// speedup vs baseline: 2.4212x; 1.0414x over previous
#include <cuda_runtime.h>
#include <cuda_fp16.h>
#include <cstdint>

// ============================================================
// Fused 4-layer MLP via mma.sync m16n8k16 f16 (fp32 accum).
//   out = relu( ((relu(x@W0^T)) @ W1^T @ W2^T) @ W3^T )
// Each warp carries 2x16 rows through all layers in registers.
// cp.async double-buffered x staging; XOR-swizzled SMEM.
// B fragments packed as uint4 in SMEM: 1 LDS.128 -> 4 MMAs.
// ============================================================

#define THREADS 128          // 4 warps/CTA
#define ROWS_PER_WARP 32     // 2 x m16 subtiles
#define TILE_ROWS 128        // 4 warps x 32 rows
#define CTAS_PER_SM 3

// dynamic SMEM layout (bytes)
#define SM_X0   0            // 128 rows x 128B (16 KB)
#define SM_X1   16384
#define SM_W0P  32768        // 256 uint4 (4 KB)
#define SM_W1P  36864        // 512 uint4 (8 KB)
#define SM_W2P  45056        // 512 uint4 (8 KB)
#define SM_W3P  53248        // 128 uint4 (2 KB)
#define SM_TOTAL 55296

static __device__ __forceinline__ uint32_t f22h2(float lo, float hi) {
    __half2 h = __floats2half2_rn(lo, hi);   // lo -> .x (low half)
    return *reinterpret_cast<uint32_t*>(&h);
}

static __device__ __forceinline__ uint32_t smem_u32(const void* p) {
    uint32_t a;
    asm("{ .reg .u64 t; cvta.to.shared.u64 t, %1; cvt.u32.u64 %0, t; }"
        : "=r"(a) : "l"(p));
    return a;
}

static __device__ __forceinline__ void mma16(float c[4], const uint32_t a[4],
                                             uint32_t b0, uint32_t b1) {
    asm volatile(
        "mma.sync.aligned.m16n8k16.row.col.f32.f16.f16.f32 "
        "{%0,%1,%2,%3}, {%4,%5,%6,%7}, {%8,%9}, {%0,%1,%2,%3};"
        : "+f"(c[0]), "+f"(c[1]), "+f"(c[2]), "+f"(c[3])
        : "r"(a[0]), "r"(a[1]), "r"(a[2]), "r"(a[3]), "r"(b0), "r"(b1));
}

// relu on packed f16x2
static __device__ __forceinline__ uint32_t hmax0(uint32_t v) {
    __half2 h = *reinterpret_cast<__half2*>(&v);
    __half2 z = __float2half2_rn(0.f);
    __half2 r = __hmax2(h, z);
    return *reinterpret_cast<uint32_t*>(&r);
}

__global__ void __launch_bounds__(THREADS, CTAS_PER_SM)
ffmlp_kernel(const float* __restrict__ x,
             const float* __restrict__ W0, const float* __restrict__ W1,
             const float* __restrict__ W2, const float* __restrict__ W3,
             float* __restrict__ out, int Brows) {
    extern __shared__ char sm[];
    uint4* w0p = reinterpret_cast<uint4*>(sm + SM_W0P);
    uint4* w1p = reinterpret_cast<uint4*>(sm + SM_W1P);
    uint4* w2p = reinterpret_cast<uint4*>(sm + SM_W2P);
    uint4* w3p = reinterpret_cast<uint4*>(sm + SM_W3P);

    const int tid = threadIdx.x;

    // ---- stage weights (fp16 pairs) ----
    // L0 with x-load permutation sigma0 (matches xa unpack below)
    for (int i = tid; i < 256; i += THREADS) {
        int u = i >> 7, j2 = (i >> 5) & 3, r = (i >> 2) & 7, m = i & 3;
        int n0 = 16 * j2 + r, n1 = n0 + 8;
        int k = 8 * m + 4 * u;
        const float* p0 = W0 + n0 * 32 + k;
        const float* p1 = W0 + n1 * 32 + k;
        uint4 v;
        v.x = f22h2(__ldg(p0 + 0), __ldg(p0 + 1));
        v.y = f22h2(__ldg(p0 + 2), __ldg(p0 + 3));
        v.z = f22h2(__ldg(p1 + 0), __ldg(p1 + 1));
        v.w = f22h2(__ldg(p1 + 2), __ldg(p1 + 3));
        w0p[i] = v;
    }
    // L1/L2: natural layout (C->A chain needs no permutation for f16 pairs)
    for (int i = tid; i < 512; i += THREADS) {
        int u = i >> 7, j2 = (i >> 5) & 3, r = (i >> 2) & 7, m = i & 3;
        int n0 = 16 * j2 + r, n1 = n0 + 8;
        int k0 = 16 * u + 2 * m;
        uint4 v;
        v.x = f22h2(__ldg(W1 + n0 * 64 + k0),     __ldg(W1 + n0 * 64 + k0 + 1));
        v.y = f22h2(__ldg(W1 + n0 * 64 + k0 + 8), __ldg(W1 + n0 * 64 + k0 + 9));
        v.z = f22h2(__ldg(W1 + n1 * 64 + k0),     __ldg(W1 + n1 * 64 + k0 + 1));
        v.w = f22h2(__ldg(W1 + n1 * 64 + k0 + 8), __ldg(W1 + n1 * 64 + k0 + 9));
        w1p[i] = v;
        v.x = f22h2(__ldg(W2 + n0 * 64 + k0),     __ldg(W2 + n0 * 64 + k0 + 1));
        v.y = f22h2(__ldg(W2 + n0 * 64 + k0 + 8), __ldg(W2 + n0 * 64 + k0 + 9));
        v.z = f22h2(__ldg(W2 + n1 * 64 + k0),     __ldg(W2 + n1 * 64 + k0 + 1));
        v.w = f22h2(__ldg(W2 + n1 * 64 + k0 + 8), __ldg(W2 + n1 * 64 + k0 + 9));
        w2p[i] = v;
    }
    // L3 with N-permutation so each thread's C covers 4 adjacent out cols:
    // block j, frag row r -> physical col 4*(r>>1) + 2*j + (r&1)
    for (int i = tid; i < 128; i += THREADS) {
        int u = i >> 5, r = (i >> 2) & 7, m = i & 3;
        int n0 = 4 * (r >> 1) + (r & 1);   // block 0
        int n1 = n0 + 2;                   // block 1
        int k0 = 16 * u + 2 * m;
        uint4 v;
        v.x = f22h2(__ldg(W3 + n0 * 64 + k0),     __ldg(W3 + n0 * 64 + k0 + 1));
        v.y = f22h2(__ldg(W3 + n0 * 64 + k0 + 8), __ldg(W3 + n0 * 64 + k0 + 9));
        v.z = f22h2(__ldg(W3 + n1 * 64 + k0),     __ldg(W3 + n1 * 64 + k0 + 1));
        v.w = f22h2(__ldg(W3 + n1 * 64 + k0 + 8), __ldg(W3 + n1 * 64 + k0 + 9));
        w3p[i] = v;
    }

    const int wid  = tid >> 5;
    const int lane = tid & 31;
    const int r = lane >> 2;      // group id (row within 8)
    const int m = lane & 3;       // thread-in-group
    const int lidx = r * 4 + m;   // packed (r,m) index

    const int ntiles = Brows / TILE_ROWS;   // B = 1M -> exact
    const uint32_t xs[2] = { smem_u32(sm + SM_X0), smem_u32(sm + SM_X1) };

    // ---- stage x tile via cp.async: chunk c of row stored at c^(row&7) ----
    auto stage_x = [&](int tile, uint32_t xbase) {
#pragma unroll
        for (int i = 0; i < 8; i++) {
            int idx = tid + i * THREADS;          // 0..1023 chunk slots
            int row = idx >> 3, c = idx & 7;
            uint32_t dst = xbase + (uint32_t)(row * 128 + ((c ^ (row & 7)) * 16));
            const float* src = x + (size_t)(tile * TILE_ROWS + row) * 32 + c * 4;
            asm volatile("cp.async.cg.shared.global [%0], [%1], 16;"
                         :: "r"(dst), "l"(src));
        }
    };

    int tile = blockIdx.x;
    int buf = 0;
    if (tile < ntiles) stage_x(tile, xs[0]);
    asm volatile("cp.async.commit_group;" ::: "memory");

    for (; tile < ntiles; tile += gridDim.x) {
        int nxt = tile + gridDim.x;
        if (nxt < ntiles) stage_x(nxt, xs[buf ^ 1]);
        asm volatile("cp.async.commit_group;" ::: "memory");
        asm volatile("cp.async.wait_group 1;" ::: "memory");   // current buf ready
        __syncthreads();

        const int row0 = tile * TILE_ROWS + wid * ROWS_PER_WARP;
        const uint32_t xb = xs[buf];

        // ---- x fragments from SMEM (swizzled LDS.128, conflict-free) ----
        uint32_t xa[2][2][4];
#pragma unroll
        for (int s = 0; s < 2; s++) {
            int rw = (wid * ROWS_PER_WARP + 16 * s + r);       // CTA-local row
            uint32_t a0 = xb + (uint32_t)(rw * 128);
            uint32_t a8 = a0 + 8 * 128;
            float4 lo0 = *reinterpret_cast<const float4*>(sm + (a0 - xs[0] + SM_X0) + 0);
            // NOTE: recompute via direct pointers below instead
            (void)lo0;
#pragma unroll
            for (int dummy = 0; dummy < 1; dummy++) { }
            const char* base0 = sm + (size_t)(buf ? SM_X1 : SM_X0) + (size_t)rw * 128;
            const char* base8 = base0 + 8 * 128;
            float4 c0 = *reinterpret_cast<const float4*>(base0 + (((2 * m + 0) ^ r) * 16));
            float4 c1 = *reinterpret_cast<const float4*>(base0 + (((2 * m + 1) ^ r) * 16));
            float4 d0 = *reinterpret_cast<const float4*>(base8 + (((2 * m + 0) ^ r) * 16));
            float4 d1 = *reinterpret_cast<const float4*>(base8 + (((2 * m + 1) ^ r) * 16));
            xa[s][0][0] = f22h2(c0.x, c0.y);  xa[s][0][2] = f22h2(c0.z, c0.w);
            xa[s][1][0] = f22h2(c1.x, c1.y);  xa[s][1][2] = f22h2(c1.z, c1.w);
            xa[s][0][1] = f22h2(d0.x, d0.y);  xa[s][0][3] = f22h2(d0.z, d0.w);
            xa[s][1][1] = f22h2(d1.x, d1.y);  xa[s][1][3] = f22h2(d1.z, d1.w);
        }

        // ---- Layer 0: [32,32] x [32,64] ----
        float c[2][8][4];
#pragma unroll
        for (int s = 0; s < 2; s++)
#pragma unroll
            for (int j = 0; j < 8; j++) { c[s][j][0] = c[s][j][1] = c[s][j][2] = c[s][j][3] = 0.f; }
#pragma unroll
        for (int u = 0; u < 2; u++) {
#pragma unroll
            for (int j2 = 0; j2 < 4; j2++) {
                uint4 bb = w0p[((u * 4 + j2) * 32) + lidx];
#pragma unroll
                for (int s = 0; s < 2; s++) {
                    mma16(c[s][2 * j2],     xa[s][u], bb.x, bb.y);
                    mma16(c[s][2 * j2 + 1], xa[s][u], bb.z, bb.w);
                }
            }
        }

        // ReLU (packed hmax2) -> A for layer 1
        uint32_t a[2][4][4];
#pragma unroll
        for (int s = 0; s < 2; s++)
#pragma unroll
            for (int u = 0; u < 4; u++) {
                a[s][u][0] = hmax0(f22h2(c[s][2*u][0],   c[s][2*u][1]));
                a[s][u][1] = hmax0(f22h2(c[s][2*u][2],   c[s][2*u][3]));
                a[s][u][2] = hmax0(f22h2(c[s][2*u+1][0], c[s][2*u+1][1]));
                a[s][u][3] = hmax0(f22h2(c[s][2*u+1][2], c[s][2*u+1][3]));
            }

        // ---- Layer 1: [32,64] x [64,64] (no activation) ----
#pragma unroll
        for (int s = 0; s < 2; s++)
#pragma unroll
            for (int j = 0; j < 8; j++) { c[s][j][0] = c[s][j][1] = c[s][j][2] = c[s][j][3] = 0.f; }
#pragma unroll
        for (int u = 0; u < 4; u++) {
#pragma unroll
            for (int j2 = 0; j2 < 4; j2++) {
                uint4 bb = w1p[((u * 4 + j2) * 32) + lidx];
#pragma unroll
                for (int s = 0; s < 2; s++) {
                    mma16(c[s][2 * j2],     a[s][u], bb.x, bb.y);
                    mma16(c[s][2 * j2 + 1], a[s][u], bb.z, bb.w);
                }
            }
        }
#pragma unroll
        for (int s = 0; s < 2; s++)
#pragma unroll
            for (int u = 0; u < 4; u++) {
                a[s][u][0] = f22h2(c[s][2*u][0],   c[s][2*u][1]);
                a[s][u][1] = f22h2(c[s][2*u][2],   c[s][2*u][3]);
                a[s][u][2] = f22h2(c[s][2*u+1][0], c[s][2*u+1][1]);
                a[s][u][3] = f22h2(c[s][2*u+1][2], c[s][2*u+1][3]);
            }

        // ---- Layer 2: [32,64] x [64,64] (no activation) ----
#pragma unroll
        for (int s = 0; s < 2; s++)
#pragma unroll
            for (int j = 0; j < 8; j++) { c[s][j][0] = c[s][j][1] = c[s][j][2] = c[s][j][3] = 0.f; }
#pragma unroll
        for (int u = 0; u < 4; u++) {
#pragma unroll
            for (int j2 = 0; j2 < 4; j2++) {
                uint4 bb = w2p[((u * 4 + j2) * 32) + lidx];
#pragma unroll
                for (int s = 0; s < 2; s++) {
                    mma16(c[s][2 * j2],     a[s][u], bb.x, bb.y);
                    mma16(c[s][2 * j2 + 1], a[s][u], bb.z, bb.w);
                }
            }
        }
#pragma unroll
        for (int s = 0; s < 2; s++)
#pragma unroll
            for (int u = 0; u < 4; u++) {
                a[s][u][0] = f22h2(c[s][2*u][0],   c[s][2*u][1]);
                a[s][u][1] = f22h2(c[s][2*u][2],   c[s][2*u][3]);
                a[s][u][2] = f22h2(c[s][2*u+1][0], c[s][2*u+1][1]);
                a[s][u][3] = f22h2(c[s][2*u+1][2], c[s][2*u+1][3]);
            }

        // ---- Layer 3: [32,64] x [64,16] (N-permuted weights) ----
        float c3[2][2][4];
#pragma unroll
        for (int s = 0; s < 2; s++)
#pragma unroll
            for (int j = 0; j < 2; j++) { c3[s][j][0] = c3[s][j][1] = c3[s][j][2] = c3[s][j][3] = 0.f; }
#pragma unroll
        for (int u = 0; u < 4; u++) {
            uint4 bb = w3p[(u * 32) + lidx];
#pragma unroll
            for (int s = 0; s < 2; s++) {
                mma16(c3[s][0], a[s][u], bb.x, bb.y);
                mma16(c3[s][1], a[s][u], bb.z, bb.w);
            }
        }

        // ---- Epilogue: ReLU + STG.128 (thread owns 4 adjacent cols) ----
#pragma unroll
        for (int s = 0; s < 2; s++) {
            int base = row0 + 16 * s;
            float4 v0, v1;
            v0.x = fmaxf(c3[s][0][0], 0.f); v0.y = fmaxf(c3[s][0][1], 0.f);
            v0.z = fmaxf(c3[s][1][0], 0.f); v0.w = fmaxf(c3[s][1][1], 0.f);
            v1.x = fmaxf(c3[s][0][2], 0.f); v1.y = fmaxf(c3[s][0][3], 0.f);
            v1.z = fmaxf(c3[s][1][2], 0.f); v1.w = fmaxf(c3[s][1][3], 0.f);
            *reinterpret_cast<float4*>(out + (size_t)(base + r) * 16 + 4 * m) = v0;
            *reinterpret_cast<float4*>(out + (size_t)(base + r + 8) * 16 + 4 * m) = v1;
        }

        buf ^= 1;
        __syncthreads();   // all reads of old buf done before next stage into it
    }
}

extern "C" void kernel_launch(void* const* d_in, const int* in_sizes, int n_in,
                              void* d_out, int out_size) {
    const float* x  = (const float*)d_in[0];
    const float* W0 = (const float*)d_in[1];
    const float* W1 = (const float*)d_in[2];
    const float* W2 = (const float*)d_in[3];
    const float* W3 = (const float*)d_in[4];
    float* out = (float*)d_out;
    int Brows = in_sizes[0] / 32;

    cudaFuncSetAttribute(ffmlp_kernel, cudaFuncAttributeMaxDynamicSharedMemorySize, SM_TOTAL);
    int ntiles = Brows / TILE_ROWS;
    int grid = CTAS_PER_SM * 148;
    if (grid > ntiles) grid = ntiles;
    if (grid < 1) grid = 1;
    ffmlp_kernel<<<grid, THREADS, SM_TOTAL>>>(x, W0, W1, W2, W3, out, Brows);
}